// round 1
// baseline (speedup 1.0000x reference)
#include <cuda_runtime.h>

#define N_B    16
#define C_DIM  512
#define HW_DIM 3136
#define D_DIM  512

// Scratch (allocation-free contract: __device__ globals)
__device__ float g_Q[(size_t)N_B * HW_DIM * D_DIM];   // [n][s][d]
__device__ float g_K[(size_t)N_B * HW_DIM * D_DIM];   // [n][s][d]
__device__ float g_V[(size_t)N_B * HW_DIM * D_DIM];   // [n][s][d]
__device__ float g_S[(size_t)N_B * D_DIM * D_DIM];    // [n][d][e]

constexpr int BM = 64, BN = 64, BK = 16;

// Generic tiled SGEMM:
//   C[m][n] = sum_k a(k,m) * b(k,n)  (+ bias[n])
// A_KMAJOR: a(k,m) = A[k*lda + m]   else a(k,m) = A[m*lda + k]
// B_KMAJOR: b(k,n) = B[k*ldb + n]   else b(k,n) = B[n*ldb + k]
// All of M, N divisible by 64; K divisible by 16; lda/ldb/ldc divisible by 4.
template <bool A_KMAJOR, bool B_KMAJOR, bool ADD_BIAS>
__global__ __launch_bounds__(256)
void gemm_kernel(const float* __restrict__ A, const float* __restrict__ B,
                 const float* __restrict__ bias, float* __restrict__ C,
                 int M, int Nn, int K, int lda, int ldb, int ldc,
                 long long strideA, long long strideB, long long strideC)
{
    __shared__ float As[BK][BM + 4];
    __shared__ float Bs[BK][BN + 4];

    const int tid = threadIdx.x;
    const int n0 = blockIdx.x * BN;
    const int m0 = blockIdx.y * BM;

    A += strideA * blockIdx.z;
    B += strideB * blockIdx.z;
    C += strideC * blockIdx.z;

    const int tx = tid & 15;   // 0..15 -> 4 columns each
    const int ty = tid >> 4;   // 0..15 -> 4 rows each

    float acc[4][4] = {};

    for (int kt = 0; kt < K; kt += BK) {
        // ---- load A tile into As[k][m] ----
        if (A_KMAJOR) {
            const int k  = tid >> 4;          // 0..15
            const int m4 = (tid & 15) * 4;    // 0..60
            float4 v = *(const float4*)(A + (long long)(kt + k) * lda + m0 + m4);
            As[k][m4 + 0] = v.x; As[k][m4 + 1] = v.y;
            As[k][m4 + 2] = v.z; As[k][m4 + 3] = v.w;
        } else {
            const int mm = tid >> 2;          // 0..63
            const int k4 = (tid & 3) * 4;     // 0,4,8,12
            float4 v = *(const float4*)(A + (long long)(m0 + mm) * lda + kt + k4);
            As[k4 + 0][mm] = v.x; As[k4 + 1][mm] = v.y;
            As[k4 + 2][mm] = v.z; As[k4 + 3][mm] = v.w;
        }
        // ---- load B tile into Bs[k][n] ----
        if (B_KMAJOR) {
            const int k  = tid >> 4;
            const int n4 = (tid & 15) * 4;
            float4 v = *(const float4*)(B + (long long)(kt + k) * ldb + n0 + n4);
            Bs[k][n4 + 0] = v.x; Bs[k][n4 + 1] = v.y;
            Bs[k][n4 + 2] = v.z; Bs[k][n4 + 3] = v.w;
        } else {
            const int nn = tid >> 2;
            const int k4 = (tid & 3) * 4;
            float4 v = *(const float4*)(B + (long long)(n0 + nn) * ldb + kt + k4);
            Bs[k4 + 0][nn] = v.x; Bs[k4 + 1][nn] = v.y;
            Bs[k4 + 2][nn] = v.z; Bs[k4 + 3][nn] = v.w;
        }
        __syncthreads();

        #pragma unroll
        for (int k = 0; k < BK; k++) {
            float4 av = *(const float4*)&As[k][ty * 4];
            float4 bv = *(const float4*)&Bs[k][tx * 4];
            float a[4] = {av.x, av.y, av.z, av.w};
            float b[4] = {bv.x, bv.y, bv.z, bv.w};
            #pragma unroll
            for (int i = 0; i < 4; i++)
                #pragma unroll
                for (int j = 0; j < 4; j++)
                    acc[i][j] += a[i] * b[j];
        }
        __syncthreads();
    }

    // ---- epilogue ----
    float bn[4] = {0.f, 0.f, 0.f, 0.f};
    if (ADD_BIAS) {
        float4 bv = *(const float4*)(bias + n0 + tx * 4);
        bn[0] = bv.x; bn[1] = bv.y; bn[2] = bv.z; bn[3] = bv.w;
    }
    #pragma unroll
    for (int i = 0; i < 4; i++) {
        const int m = m0 + ty * 4 + i;
        float4 o;
        o.x = acc[i][0] + bn[0];
        o.y = acc[i][1] + bn[1];
        o.z = acc[i][2] + bn[2];
        o.w = acc[i][3] + bn[3];
        *(float4*)(C + (long long)m * ldc + n0 + tx * 4) = o;
    }
}

// Softmax over rows of length D_DIM (=512). One block (256 threads) per row.
__global__ __launch_bounds__(256)
void softmax_kernel(float* __restrict__ S)
{
    const long long row = blockIdx.x;
    float* p = S + row * D_DIM;
    const int t = threadIdx.x;

    const float a = p[t];
    const float b = p[t + 256];

    __shared__ float red_max[8];
    __shared__ float red_sum[8];

    // row max
    float m = fmaxf(a, b);
    #pragma unroll
    for (int o = 16; o > 0; o >>= 1)
        m = fmaxf(m, __shfl_xor_sync(0xffffffffu, m, o));
    if ((t & 31) == 0) red_max[t >> 5] = m;
    __syncthreads();
    float rowmax = red_max[0];
    #pragma unroll
    for (int i = 1; i < 8; i++) rowmax = fmaxf(rowmax, red_max[i]);

    // exp + row sum
    const float ea = __expf(a - rowmax);
    const float eb = __expf(b - rowmax);
    float s = ea + eb;
    #pragma unroll
    for (int o = 16; o > 0; o >>= 1)
        s += __shfl_xor_sync(0xffffffffu, s, o);
    if ((t & 31) == 0) red_sum[t >> 5] = s;
    __syncthreads();
    float tot = 0.f;
    #pragma unroll
    for (int i = 0; i < 8; i++) tot += red_sum[i];
    const float inv = 1.0f / tot;

    p[t]       = ea * inv;
    p[t + 256] = eb * inv;
}

extern "C" void kernel_launch(void* const* d_in, const int* in_sizes, int n_in,
                              void* d_out, int out_size)
{
    (void)in_sizes; (void)n_in; (void)out_size;
    const float* bf = (const float*)d_in[0];  // [N, C, HW]
    const float* Wq = (const float*)d_in[1];  // [D, C]
    const float* bq = (const float*)d_in[2];  // [D]
    const float* Wk = (const float*)d_in[3];
    const float* bk = (const float*)d_in[4];
    const float* Wv = (const float*)d_in[5];
    const float* bv = (const float*)d_in[6];
    float* out = (float*)d_out;               // [N, D, HW]

    float *Qp, *Kp, *Vp, *Sp;
    cudaGetSymbolAddress((void**)&Qp, g_Q);
    cudaGetSymbolAddress((void**)&Kp, g_K);
    cudaGetSymbolAddress((void**)&Vp, g_V);
    cudaGetSymbolAddress((void**)&Sp, g_S);

    const dim3 blk(256);

    // 1) Q/K/V projections: Out[n][s][d] = sum_c x(k=c,m=s) * W(n=d,k=c) + b[d]
    //    A = batch_flat (k-major: bf[c*HW + s]), B = W ([d][c], not k-major)
    const dim3 g_qkv(D_DIM / BN, HW_DIM / BM, N_B);
    const long long sA_x = (long long)C_DIM * HW_DIM;
    const long long sC_q = (long long)HW_DIM * D_DIM;
    gemm_kernel<true, false, true><<<g_qkv, blk>>>(
        bf, Wq, bq, Qp, HW_DIM, D_DIM, C_DIM, HW_DIM, C_DIM, D_DIM, sA_x, 0, sC_q);
    gemm_kernel<true, false, true><<<g_qkv, blk>>>(
        bf, Wk, bk, Kp, HW_DIM, D_DIM, C_DIM, HW_DIM, C_DIM, D_DIM, sA_x, 0, sC_q);
    gemm_kernel<true, false, true><<<g_qkv, blk>>>(
        bf, Wv, bv, Vp, HW_DIM, D_DIM, C_DIM, HW_DIM, C_DIM, D_DIM, sA_x, 0, sC_q);

    // 2) scores: S[n][d][e] = sum_s Q[s][d] * K[s][e]  (both k-major over s)
    const dim3 g_sc(D_DIM / BN, D_DIM / BM, N_B);
    const long long sS = (long long)D_DIM * D_DIM;
    gemm_kernel<true, true, false><<<g_sc, blk>>>(
        Qp, Kp, nullptr, Sp, D_DIM, D_DIM, HW_DIM, D_DIM, D_DIM, D_DIM, sC_q, sC_q, sS);

    // 3) softmax over last dim of S (N*D rows of length D)
    softmax_kernel<<<N_B * D_DIM, 256>>>(Sp);

    // 4) out: O[n][d][s] = sum_e S[d][e] * V[s][e]  (both NOT k-major)
    const dim3 g_out(HW_DIM / BN, D_DIM / BM, N_B);
    gemm_kernel<false, false, false><<<g_out, blk>>>(
        Sp, Vp, nullptr, out, D_DIM, HW_DIM, D_DIM, D_DIM, D_DIM, HW_DIM,
        sS, sC_q, (long long)D_DIM * HW_DIM);
}

// round 2
// speedup vs baseline: 1.1583x; 1.1583x over previous
#include <cuda_runtime.h>

#define N_B    16
#define C_DIM  512
#define HW_DIM 3136
#define D_DIM  512

// Scratch (allocation-free contract: __device__ globals)
__device__ float g_Q[(size_t)N_B * HW_DIM * D_DIM];   // [n][s][d]
__device__ float g_K[(size_t)N_B * HW_DIM * D_DIM];   // [n][s][d]
__device__ float g_V[(size_t)N_B * HW_DIM * D_DIM];   // [n][s][d]
__device__ float g_S[(size_t)N_B * D_DIM * D_DIM];    // [n][d][e]

constexpr int BM = 128, BN = 128, BK = 16;
constexpr int SROW = BM + 4;   // padded smem row

// ---- tile load: global -> registers (2 float4 per thread) ----
template <bool KMAJ>
__device__ __forceinline__ void load_frag(const float* __restrict__ P, int kt,
                                          int base0, int rows, int ld, int tid,
                                          float4 r[2])
{
    if (KMAJ) {
        // P[k*ld + m]; thread covers k = tid>>4, m = base0 + (tid&15)*8 .. +7
        const int k = tid >> 4;
        int m = base0 + (tid & 15) * 8;
        m = min(m, rows - 8);                      // rows % 8 == 0 always
        const float* p = P + (long long)(kt + k) * ld + m;
        r[0] = *(const float4*)p;
        r[1] = *(const float4*)(p + 4);
    } else {
        // P[m*ld + k]; thread covers m = base0 + (tid>>1), k = kt + (tid&1)*8 .. +7
        int m = base0 + (tid >> 1);
        m = min(m, rows - 1);
        const int kk = (tid & 1) * 8;
        const float* p = P + (long long)m * ld + kt + kk;
        r[0] = *(const float4*)p;
        r[1] = *(const float4*)(p + 4);
    }
}

// ---- tile store: registers -> smem (always smem[k][m]) ----
template <bool KMAJ>
__device__ __forceinline__ void store_frag(float Sm[BK][SROW], int tid,
                                           const float4 r[2])
{
    if (KMAJ) {
        const int k = tid >> 4;
        const int m = (tid & 15) * 8;
        *(float4*)&Sm[k][m]     = r[0];
        *(float4*)&Sm[k][m + 4] = r[1];
    } else {
        const int m  = tid >> 1;
        const int kk = (tid & 1) * 8;
        Sm[kk + 0][m] = r[0].x; Sm[kk + 1][m] = r[0].y;
        Sm[kk + 2][m] = r[0].z; Sm[kk + 3][m] = r[0].w;
        Sm[kk + 4][m] = r[1].x; Sm[kk + 5][m] = r[1].y;
        Sm[kk + 6][m] = r[1].z; Sm[kk + 7][m] = r[1].w;
    }
}

// Generic tiled SGEMM: C[m][n] = sum_k a(k,m)*b(k,n) (+ bias[n])
// A_KMAJOR: a(k,m)=A[k*lda+m] else A[m*lda+k]; likewise B.
// All dims divisible by 8; K divisible by 16.
template <bool A_KMAJOR, bool B_KMAJOR, bool ADD_BIAS>
__global__ __launch_bounds__(256, 2)
void gemm_kernel(const float* __restrict__ A, const float* __restrict__ B,
                 const float* __restrict__ bias, float* __restrict__ C,
                 int M, int Nn, int K, int lda, int ldb, int ldc,
                 long long strideA, long long strideB, long long strideC)
{
    __shared__ float As[BK][SROW];
    __shared__ float Bs[BK][SROW];

    const int tid = threadIdx.x;
    const int n0 = blockIdx.x * BN;
    const int m0 = blockIdx.y * BM;

    A += strideA * blockIdx.z;
    B += strideB * blockIdx.z;
    C += strideC * blockIdx.z;

    const int tx = tid & 15;   // col group: 8 cols each
    const int ty = tid >> 4;   // row group: 8 rows each

    float acc[8][8] = {};
    float4 ra[2], rb[2];

    load_frag<A_KMAJOR>(A, 0, m0, M,  lda, tid, ra);
    load_frag<B_KMAJOR>(B, 0, n0, Nn, ldb, tid, rb);

    for (int kt = 0; kt < K; kt += BK) {
        store_frag<A_KMAJOR>(As, tid, ra);
        store_frag<B_KMAJOR>(Bs, tid, rb);
        __syncthreads();

        if (kt + BK < K) {
            load_frag<A_KMAJOR>(A, kt + BK, m0, M,  lda, tid, ra);
            load_frag<B_KMAJOR>(B, kt + BK, n0, Nn, ldb, tid, rb);
        }

        #pragma unroll
        for (int k = 0; k < BK; k++) {
            float4 a0 = *(const float4*)&As[k][ty * 8];
            float4 a1 = *(const float4*)&As[k][ty * 8 + 4];
            float4 b0 = *(const float4*)&Bs[k][tx * 8];
            float4 b1 = *(const float4*)&Bs[k][tx * 8 + 4];
            float a[8] = {a0.x, a0.y, a0.z, a0.w, a1.x, a1.y, a1.z, a1.w};
            float b[8] = {b0.x, b0.y, b0.z, b0.w, b1.x, b1.y, b1.z, b1.w};
            #pragma unroll
            for (int i = 0; i < 8; i++)
                #pragma unroll
                for (int j = 0; j < 8; j++)
                    acc[i][j] += a[i] * b[j];
        }
        __syncthreads();
    }

    // ---- epilogue ----
    float bn[8] = {};
    const int nbase = n0 + tx * 8;
    const bool n_ok = (nbase < Nn);            // Nn % 8 == 0 -> all-or-nothing
    if (ADD_BIAS && n_ok) {
        float4 b0 = *(const float4*)(bias + nbase);
        float4 b1 = *(const float4*)(bias + nbase + 4);
        bn[0]=b0.x; bn[1]=b0.y; bn[2]=b0.z; bn[3]=b0.w;
        bn[4]=b1.x; bn[5]=b1.y; bn[6]=b1.z; bn[7]=b1.w;
    }
    if (n_ok) {
        #pragma unroll
        for (int i = 0; i < 8; i++) {
            const int m = m0 + ty * 8 + i;
            if (m < M) {
                float4 o0, o1;
                o0.x = acc[i][0] + bn[0]; o0.y = acc[i][1] + bn[1];
                o0.z = acc[i][2] + bn[2]; o0.w = acc[i][3] + bn[3];
                o1.x = acc[i][4] + bn[4]; o1.y = acc[i][5] + bn[5];
                o1.z = acc[i][6] + bn[6]; o1.w = acc[i][7] + bn[7];
                float* cp = C + (long long)m * ldc + nbase;
                *(float4*)cp       = o0;
                *(float4*)(cp + 4) = o1;
            }
        }
    }
}

// Softmax over rows of length D_DIM (=512). One block (256 threads) per row.
__global__ __launch_bounds__(256)
void softmax_kernel(float* __restrict__ S)
{
    const long long row = blockIdx.x;
    float* p = S + row * D_DIM;
    const int t = threadIdx.x;

    const float a = p[t];
    const float b = p[t + 256];

    __shared__ float red_max[8];
    __shared__ float red_sum[8];

    float m = fmaxf(a, b);
    #pragma unroll
    for (int o = 16; o > 0; o >>= 1)
        m = fmaxf(m, __shfl_xor_sync(0xffffffffu, m, o));
    if ((t & 31) == 0) red_max[t >> 5] = m;
    __syncthreads();
    float rowmax = red_max[0];
    #pragma unroll
    for (int i = 1; i < 8; i++) rowmax = fmaxf(rowmax, red_max[i]);

    const float ea = __expf(a - rowmax);
    const float eb = __expf(b - rowmax);
    float s = ea + eb;
    #pragma unroll
    for (int o = 16; o > 0; o >>= 1)
        s += __shfl_xor_sync(0xffffffffu, s, o);
    if ((t & 31) == 0) red_sum[t >> 5] = s;
    __syncthreads();
    float tot = 0.f;
    #pragma unroll
    for (int i = 0; i < 8; i++) tot += red_sum[i];
    const float inv = 1.0f / tot;

    p[t]       = ea * inv;
    p[t + 256] = eb * inv;
}

extern "C" void kernel_launch(void* const* d_in, const int* in_sizes, int n_in,
                              void* d_out, int out_size)
{
    (void)in_sizes; (void)n_in; (void)out_size;
    const float* bf = (const float*)d_in[0];  // [N, C, HW]
    const float* Wq = (const float*)d_in[1];  // [D, C]
    const float* bq = (const float*)d_in[2];  // [D]
    const float* Wk = (const float*)d_in[3];
    const float* bk = (const float*)d_in[4];
    const float* Wv = (const float*)d_in[5];
    const float* bv = (const float*)d_in[6];
    float* out = (float*)d_out;               // [N, D, HW]

    float *Qp, *Kp, *Vp, *Sp;
    cudaGetSymbolAddress((void**)&Qp, g_Q);
    cudaGetSymbolAddress((void**)&Kp, g_K);
    cudaGetSymbolAddress((void**)&Vp, g_V);
    cudaGetSymbolAddress((void**)&Sp, g_S);

    const dim3 blk(256);
    const long long sA_x = (long long)C_DIM * HW_DIM;
    const long long sQ   = (long long)HW_DIM * D_DIM;
    const long long sS   = (long long)D_DIM * D_DIM;

    // 1) Q/K/V projections: Out[n][s][d] = sum_c x(k=c,m=s) * W(n=d,k=c) + b[d]
    //    A = batch_flat (k-major), B = W[d][c] (not k-major)
    const dim3 g_qkv(D_DIM / BN, (HW_DIM + BM - 1) / BM, N_B);   // (4, 25, 16)
    gemm_kernel<true, false, true><<<g_qkv, blk>>>(
        bf, Wq, bq, Qp, HW_DIM, D_DIM, C_DIM, HW_DIM, C_DIM, D_DIM, sA_x, 0, sQ);
    gemm_kernel<true, false, true><<<g_qkv, blk>>>(
        bf, Wk, bk, Kp, HW_DIM, D_DIM, C_DIM, HW_DIM, C_DIM, D_DIM, sA_x, 0, sQ);
    gemm_kernel<true, false, true><<<g_qkv, blk>>>(
        bf, Wv, bv, Vp, HW_DIM, D_DIM, C_DIM, HW_DIM, C_DIM, D_DIM, sA_x, 0, sQ);

    // 2) scores: S[n][d][e] = sum_s Q[s][d] * K[s][e]  (both k-major over s)
    const dim3 g_sc(D_DIM / BN, D_DIM / BM, N_B);                // (4, 4, 16)
    gemm_kernel<true, true, false><<<g_sc, blk>>>(
        Qp, Kp, nullptr, Sp, D_DIM, D_DIM, HW_DIM, D_DIM, D_DIM, D_DIM, sQ, sQ, sS);

    // 3) softmax over last dim of S (N*D rows of length D)
    softmax_kernel<<<N_B * D_DIM, 256>>>(Sp);

    // 4) out: O[n][d][s] = sum_e S[d][e] * V[s][e]  (both not k-major)
    const dim3 g_out((HW_DIM + BN - 1) / BN, D_DIM / BM, N_B);   // (25, 4, 16)
    gemm_kernel<false, false, false><<<g_out, blk>>>(
        Sp, Vp, nullptr, out, D_DIM, HW_DIM, D_DIM, D_DIM, D_DIM, HW_DIM,
        sS, sQ, (long long)D_DIM * HW_DIM);
}